// round 6
// baseline (speedup 1.0000x reference)
#include <cuda_runtime.h>
#include <cuda_bf16.h>
#include <math.h>

// ------------------------ problem constants ------------------------
#define BB_   4
#define NPROP 2000
#define NGT   20
#define FEAT  12544          // 256*7*7
#define HID   1024
#define NCLS  81             // NUM_LABELS + 1
#define NOUT  85             // 81 cls + 4 box
#define NOUTP 128            // padded head width
#define NSAMP 512
#define NPOS  128
#define NNEG  384
#define MROWS (BB_ * NSAMP)  // 2048
#define KSPLIT 2

// ------------------------ device scratch (no allocs allowed) ------------------------
__device__ float          g_part[KSPLIT * MROWS * HID];  // split-K partials
__device__ __nv_bfloat16  g_Xb[MROWS * FEAT];            // gathered + bf16 features
__device__ __nv_bfloat16  g_W1b[FEAT * HID];
__device__ __nv_bfloat16  g_W2b[HID * HID];
__device__ __nv_bfloat16  g_Wcb[HID * NOUTP];
__device__ __nv_bfloat16  g_h1b[MROWS * HID];
__device__ __nv_bfloat16  g_h2b[MROWS * HID];
__device__ float          g_ld[MROWS * NOUT];
__device__ float          g_bcb[NOUTP];
__device__ int            g_sel[MROWS];
__device__ int            g_tgt[MROWS];
__device__ float          g_gtd[MROWS * 4];

// ------------------------ helpers ------------------------
__device__ __forceinline__ unsigned smem_u32(const void* p) {
    return (unsigned)__cvta_generic_to_shared(p);
}
#define CP_ASYNC16(dst_u32, src_ptr) \
    asm volatile("cp.async.cg.shared.global [%0], [%1], 16;" \
                 :: "r"(dst_u32), "l"(src_ptr))
#define CP_COMMIT() asm volatile("cp.async.commit_group;")

__device__ __forceinline__ void ldsm4(unsigned* r, unsigned addr) {
    asm volatile("ldmatrix.sync.aligned.m8n8.x4.shared.b16 {%0,%1,%2,%3}, [%4];"
                 : "=r"(r[0]), "=r"(r[1]), "=r"(r[2]), "=r"(r[3]) : "r"(addr));
}
__device__ __forceinline__ void ldsm4t(unsigned* r, unsigned addr) {
    asm volatile("ldmatrix.sync.aligned.m8n8.x4.trans.shared.b16 {%0,%1,%2,%3}, [%4];"
                 : "=r"(r[0]), "=r"(r[1]), "=r"(r[2]), "=r"(r[3]) : "r"(addr));
}

// ------------------------ small kernels ------------------------

__global__ void zero_out_kernel(float* out) {
    if (threadIdx.x < 2) out[threadIdx.x] = 0.0f;
}

// Per image: IoU matching + threshold labeling + deterministic first-k sampling.
__global__ void select_kernel(const float* __restrict__ proposals,
                              const float* __restrict__ gt_boxes,
                              const int*   __restrict__ gt_labels) {
    int b = blockIdx.x;
    int t = threadIdx.x;  // 256 threads

    __shared__ float gs[NGT][4];
    __shared__ int   glab[NGT];
    __shared__ int   lab[NPROP];
    __shared__ float gtd_sh[NPROP][4];

    if (t < NGT * 4) ((float*)gs)[t] = gt_boxes[b * NGT * 4 + t];
    if (t < NGT)     glab[t] = gt_labels[b * NGT + t];
    for (int i = t; i < NSAMP; i += 256) g_sel[b * NSAMP + i] = -1;
    __syncthreads();

    for (int n = t; n < NPROP; n += 256) {
        const float* p = proposals + (size_t)(b * NPROP + n) * 4;
        float p0 = p[0], p1 = p[1], p2 = p[2], p3 = p[3];
        float ap = (p2 - p0) * (p3 - p1);
        float best = -1.0f; int bi = 0;
        #pragma unroll
        for (int gi = 0; gi < NGT; gi++) {
            float x1 = fmaxf(p0, gs[gi][0]);
            float y1 = fmaxf(p1, gs[gi][1]);
            float x2 = fminf(p2, gs[gi][2]);
            float y2 = fminf(p3, gs[gi][3]);
            float iw = fmaxf(x2 - x1, 0.0f);
            float ih = fmaxf(y2 - y1, 0.0f);
            float inter = iw * ih;
            float ag = (gs[gi][2] - gs[gi][0]) * (gs[gi][3] - gs[gi][1]);
            float iou = inter / (ap + ag - inter);
            if (iou > best) { best = iou; bi = gi; }  // first-max wins
        }
        bool fg = best > 0.5f;
        lab[n] = fg ? glab[bi] : 0;

        float pw = p2 - p0, ph = p3 - p1;
        float pcx = p0 + 0.5f * pw, pcy = p1 + 0.5f * ph;
        float gw = gs[bi][2] - gs[bi][0], gh = gs[bi][3] - gs[bi][1];
        float gcx = 0.5f * (gs[bi][0] + gs[bi][2]);
        float gcy = 0.5f * (gs[bi][1] + gs[bi][3]);
        gtd_sh[n][0] = (gcx - pcx) / pw;
        gtd_sh[n][1] = (gcy - pcy) / ph;
        gtd_sh[n][2] = logf(gw / pw);
        gtd_sh[n][3] = logf(gh / ph);
    }
    __syncthreads();

    if (t == 0) {
        int cpos = 0, cneg = 0;
        for (int n = 0; n < NPROP; n++) {
            int l = lab[n];
            if (l > 0) {
                if (cpos < NPOS) {
                    int s = b * NSAMP + cpos; cpos++;
                    g_sel[s] = b * NPROP + n;
                    g_tgt[s] = l;
                    g_gtd[s * 4 + 0] = gtd_sh[n][0];
                    g_gtd[s * 4 + 1] = gtd_sh[n][1];
                    g_gtd[s * 4 + 2] = gtd_sh[n][2];
                    g_gtd[s * 4 + 3] = gtd_sh[n][3];
                }
            } else {
                if (cneg < NNEG) {
                    int s = b * NSAMP + NPOS + cneg; cneg++;
                    g_sel[s] = b * NPROP + n;
                    g_tgt[s] = 0;
                }
            }
            if (cpos >= NPOS && cneg >= NNEG) break;
        }
    }
}

// Gather selected rows of X and convert fp32 -> bf16 (zero rows for unused slots)
__global__ void cvt_gather_kernel(const float* __restrict__ X) {
    int i = blockIdx.x * 256 + threadIdx.x;        // float4 index
    const int R4 = FEAT / 4;
    if (i >= MROWS * R4) return;
    int r = i / R4, c = i - r * R4;
    int idx = g_sel[r];
    float4 v = make_float4(0.f, 0.f, 0.f, 0.f);
    if (idx >= 0) v = ((const float4*)X)[(size_t)idx * R4 + c];
    __nv_bfloat162* dst = (__nv_bfloat162*)g_Xb;
    dst[2 * i]     = __floats2bfloat162_rn(v.x, v.y);
    dst[2 * i + 1] = __floats2bfloat162_rn(v.z, v.w);
}

// Generic fp32 -> bf16
__global__ void cvt_kernel(const float4* __restrict__ src, __nv_bfloat162* __restrict__ dst, int n4) {
    int i = blockIdx.x * 256 + threadIdx.x;
    if (i < n4) {
        float4 v = src[i];
        dst[2 * i]     = __floats2bfloat162_rn(v.x, v.y);
        dst[2 * i + 1] = __floats2bfloat162_rn(v.z, v.w);
    }
}

// Concatenate [Wc | Wb | 0pad] -> bf16 Wcb[k*128+c], biases fp32
__global__ void build_wcb_kernel(const float* __restrict__ Wc, const float* __restrict__ bc,
                                 const float* __restrict__ Wb, const float* __restrict__ bb) {
    int i = blockIdx.x * 256 + threadIdx.x;
    if (i < HID * NOUTP) {
        int k = i / NOUTP, c = i % NOUTP;
        float v = 0.0f;
        if (c < NCLS)      v = Wc[k * NCLS + c];
        else if (c < NOUT) v = Wb[k * 4 + (c - NCLS)];
        g_Wcb[i] = __float2bfloat16(v);
    }
    if (i < NOUTP) {
        float v = 0.0f;
        if (i < NCLS)      v = bc[i];
        else if (i < NOUT) v = bb[i - NCLS];
        g_bcb[i] = v;
    }
}

// split-K reduce: h1b = bf16(relu(part0 + part1 + bias))
__global__ void reduce_h1_kernel(const float* __restrict__ bias) {
    int i = (blockIdx.x * 256 + threadIdx.x) * 4;
    if (i < MROWS * HID) {
        float4 a = *(const float4*)(g_part + i);
        float4 b = *(const float4*)(g_part + MROWS * HID + i);
        float4 bs = *(const float4*)(bias + (i & (HID - 1)));
        __nv_bfloat162 lo = __floats2bfloat162_rn(fmaxf(a.x + b.x + bs.x, 0.0f),
                                                  fmaxf(a.y + b.y + bs.y, 0.0f));
        __nv_bfloat162 hi = __floats2bfloat162_rn(fmaxf(a.z + b.z + bs.z, 0.0f),
                                                  fmaxf(a.w + b.w + bs.w, 0.0f));
        *(__nv_bfloat162*)(g_h1b + i)     = lo;
        *(__nv_bfloat162*)(g_h1b + i + 2) = hi;
    }
}

// ------------------------ bf16 tensor-core GEMM ------------------------
// Block tile 128x128x32, 256 threads (8 warps, 32x64 warp tiles),
// double-buffered cp.async, ldmatrix fragment loads, m16n8k16 bf16 MMA.
#define BM 128
#define BN 128
#define BKT 32
#define ASTR 40    // As row stride (bf16): 80B -> conflict-free ldmatrix
#define BSTR 136   // Bs row stride (bf16): 272B -> conflict-free ldmatrix

template <bool RELU, bool BIAS, bool OBF16>
__global__ __launch_bounds__(256, 2)
void mma_gemm(const __nv_bfloat16* __restrict__ A, int lda,
              const __nv_bfloat16* __restrict__ B, int ldb,
              const float* __restrict__ bias,
              void* __restrict__ Cv, int ldc, int Nvalid, int Ksub, size_t c_zstride) {
    __shared__ __nv_bfloat16 As[2][BM][ASTR];
    __shared__ __nv_bfloat16 Bs[2][BKT][BSTR];

    const int tid  = threadIdx.x;
    const int lane = tid & 31;
    const int w    = tid >> 5;
    const int wm   = w >> 1;   // 0..3
    const int wn   = w & 1;    // 0..1
    const int bm   = blockIdx.y * BM;
    const int bn   = blockIdx.x * BN;
    const int koff = blockIdx.z * Ksub;

    // A staging: row = tid>>1, 16 bf16 at (tid&1)*16
    const int ar = tid >> 1;
    const int ac = (tid & 1) * 16;
    const __nv_bfloat16* arow = A + (size_t)(bm + ar) * (size_t)lda + koff + ac;

    // B staging: k-row = tid>>3, 16 bf16 at (tid&7)*16
    const int bkr = tid >> 3;
    const int bcc = (tid & 7) * 16;
    const __nv_bfloat16* brow = B + (size_t)(koff + bkr) * (size_t)ldb + bn + bcc;

    float acc[2][8][4];
    #pragma unroll
    for (int i = 0; i < 2; i++)
        #pragma unroll
        for (int j = 0; j < 8; j++)
            #pragma unroll
            for (int q = 0; q < 4; q++) acc[i][j][q] = 0.0f;

    const int T = Ksub / BKT;

    auto load_stage = [&](int s, int kt) {
        int k0 = kt * BKT;
        CP_ASYNC16(smem_u32(&As[s][ar][ac]),     arow + k0);
        CP_ASYNC16(smem_u32(&As[s][ar][ac + 8]), arow + k0 + 8);
        const __nv_bfloat16* bs = brow + (size_t)k0 * (size_t)ldb;
        CP_ASYNC16(smem_u32(&Bs[s][bkr][bcc]),     bs);
        CP_ASYNC16(smem_u32(&Bs[s][bkr][bcc + 8]), bs + 8);
        CP_COMMIT();
    };

    load_stage(0, 0);

    // ldmatrix lane addressing
    const int a_r  = wm * 32 + (lane & 15);      // +i*16
    const int a_c  = (lane >> 4) * 8;            // +kk*16
    const int b_r  = (lane & 7) + ((lane >> 3) & 1) * 8;  // +kk*16
    const int b_c  = wn * 64 + (lane >> 4) * 8;  // +jj*16

    for (int t = 0; t < T; t++) {
        if (t + 1 < T) {
            load_stage((t + 1) & 1, t + 1);
            asm volatile("cp.async.wait_group 1;");
        } else {
            asm volatile("cp.async.wait_group 0;");
        }
        __syncthreads();

        const int s = t & 1;
        #pragma unroll
        for (int kk = 0; kk < 2; kk++) {
            unsigned a[2][4];
            #pragma unroll
            for (int i = 0; i < 2; i++)
                ldsm4(a[i], smem_u32(&As[s][a_r + i * 16][a_c + kk * 16]));

            unsigned b[8][2];
            #pragma unroll
            for (int jj = 0; jj < 4; jj++) {
                unsigned r[4];
                ldsm4t(r, smem_u32(&Bs[s][b_r + kk * 16][b_c + jj * 16]));
                b[jj * 2][0] = r[0];     b[jj * 2][1] = r[1];
                b[jj * 2 + 1][0] = r[2]; b[jj * 2 + 1][1] = r[3];
            }

            #pragma unroll
            for (int i = 0; i < 2; i++)
                #pragma unroll
                for (int j = 0; j < 8; j++) {
                    asm volatile(
                        "mma.sync.aligned.m16n8k16.row.col.f32.bf16.bf16.f32 "
                        "{%0,%1,%2,%3}, {%4,%5,%6,%7}, {%8,%9}, {%0,%1,%2,%3};"
                        : "+f"(acc[i][j][0]), "+f"(acc[i][j][1]),
                          "+f"(acc[i][j][2]), "+f"(acc[i][j][3])
                        : "r"(a[i][0]), "r"(a[i][1]), "r"(a[i][2]), "r"(a[i][3]),
                          "r"(b[j][0]), "r"(b[j][1]));
                }
        }
        __syncthreads();
    }

    if (c_zstride) Cv = (void*)((float*)Cv + (size_t)blockIdx.z * c_zstride);

    // ---- epilogue ----
    const int row0 = bm + wm * 32 + (lane >> 2);
    const int col0 = bn + wn * 64 + (lane & 3) * 2;
    #pragma unroll
    for (int i = 0; i < 2; i++) {
        #pragma unroll
        for (int j = 0; j < 8; j++) {
            int r = row0 + i * 16;
            int c = col0 + j * 8;
            float v0 = acc[i][j][0], v1 = acc[i][j][1];
            float v2 = acc[i][j][2], v3 = acc[i][j][3];
            if (BIAS) {
                float bs0 = __ldg(&bias[c]), bs1 = __ldg(&bias[c + 1]);
                v0 += bs0; v1 += bs1; v2 += bs0; v3 += bs1;
            }
            if (RELU) {
                v0 = fmaxf(v0, 0.f); v1 = fmaxf(v1, 0.f);
                v2 = fmaxf(v2, 0.f); v3 = fmaxf(v3, 0.f);
            }
            if (OBF16) {
                __nv_bfloat16* Cb = (__nv_bfloat16*)Cv;
                *(__nv_bfloat162*)(Cb + (size_t)r * ldc + c)       = __floats2bfloat162_rn(v0, v1);
                *(__nv_bfloat162*)(Cb + (size_t)(r + 8) * ldc + c) = __floats2bfloat162_rn(v2, v3);
            } else if (!BIAS) {
                float* Cf = (float*)Cv;
                *(float2*)(Cf + (size_t)r * ldc + c)       = make_float2(v0, v1);
                *(float2*)(Cf + (size_t)(r + 8) * ldc + c) = make_float2(v2, v3);
            } else {
                float* Cf = (float*)Cv;
                if (c < Nvalid)     Cf[(size_t)r * ldc + c]           = v0;
                if (c + 1 < Nvalid) Cf[(size_t)r * ldc + c + 1]       = v1;
                if (c < Nvalid)     Cf[(size_t)(r + 8) * ldc + c]     = v2;
                if (c + 1 < Nvalid) Cf[(size_t)(r + 8) * ldc + c + 1] = v3;
            }
        }
    }
}

// ------------------------ loss ------------------------
__global__ void loss_kernel(float* __restrict__ out) {
    int r = blockIdx.x;
    if (g_sel[r] < 0) return;
    int t = threadIdx.x;  // 128

    __shared__ float red[128];
    __shared__ float pv[NCLS];

    float l = (t < NCLS) ? g_ld[r * NOUT + t] : -INFINITY;

    red[t] = l; __syncthreads();
    #pragma unroll
    for (int s = 64; s > 0; s >>= 1) {
        if (t < s) red[t] = fmaxf(red[t], red[t + s]);
        __syncthreads();
    }
    float m1 = red[0]; __syncthreads();

    float e = (t < NCLS) ? expf(l - m1) : 0.0f;
    red[t] = e; __syncthreads();
    #pragma unroll
    for (int s = 64; s > 0; s >>= 1) {
        if (t < s) red[t] += red[t + s];
        __syncthreads();
    }
    float S1 = red[0]; __syncthreads();

    float p = e / S1;
    if (t < NCLS) pv[t] = p;

    red[t] = (t < NCLS) ? p : -INFINITY; __syncthreads();
    #pragma unroll
    for (int s = 64; s > 0; s >>= 1) {
        if (t < s) red[t] = fmaxf(red[t], red[t + s]);
        __syncthreads();
    }
    float m2 = red[0]; __syncthreads();

    red[t] = (t < NCLS) ? expf(p - m2) : 0.0f; __syncthreads();
    #pragma unroll
    for (int s = 64; s > 0; s >>= 1) {
        if (t < s) red[t] += red[t + s];
        __syncthreads();
    }
    float S2 = red[0];

    if (t == 0) {
        float lse2 = logf(S2) + m2;
        int tgt = g_tgt[r];
        float nll = -(pv[tgt] - lse2);
        atomicAdd(out, nll * (1.0f / (float)MROWS));
        if (tgt > 0) {
            float s = 0.0f;
            #pragma unroll
            for (int j = 0; j < 4; j++) {
                float d = g_ld[r * NOUT + NCLS + j] - g_gtd[r * 4 + j];
                float ad = fabsf(d);
                s += (ad < 1.0f) ? 0.5f * d * d : ad - 0.5f;
            }
            atomicAdd(out + 1, s * (1.0f / (float)MROWS));
        }
    }
}

// ------------------------ host launcher ------------------------
extern "C" void kernel_launch(void* const* d_in, const int* in_sizes, int n_in,
                              void* d_out, int out_size) {
    const float* X         = (const float*)d_in[0];
    const float* proposals = (const float*)d_in[1];
    const float* gt_boxes  = (const float*)d_in[2];
    const int*   gt_labels = (const int*)  d_in[3];
    const float* W1 = (const float*)d_in[4];
    const float* b1 = (const float*)d_in[5];
    const float* W2 = (const float*)d_in[6];
    const float* b2 = (const float*)d_in[7];
    const float* Wc = (const float*)d_in[8];
    const float* bc = (const float*)d_in[9];
    const float* Wb = (const float*)d_in[10];
    const float* bb = (const float*)d_in[11];
    float* out = (float*)d_out;

    float *part, *ldp, *bcb;
    __nv_bfloat16 *xb, *w1b, *w2b, *wcb, *h1b, *h2b;
    cudaGetSymbolAddress((void**)&part, g_part);
    cudaGetSymbolAddress((void**)&xb,   g_Xb);
    cudaGetSymbolAddress((void**)&w1b,  g_W1b);
    cudaGetSymbolAddress((void**)&w2b,  g_W2b);
    cudaGetSymbolAddress((void**)&wcb,  g_Wcb);
    cudaGetSymbolAddress((void**)&h1b,  g_h1b);
    cudaGetSymbolAddress((void**)&h2b,  g_h2b);
    cudaGetSymbolAddress((void**)&ldp,  g_ld);
    cudaGetSymbolAddress((void**)&bcb,  g_bcb);

    zero_out_kernel<<<1, 32>>>(out);
    select_kernel<<<BB_, 256>>>(proposals, gt_boxes, gt_labels);

    // conversions
    cvt_gather_kernel<<<(MROWS * (FEAT / 4) + 255) / 256, 256>>>(X);
    cvt_kernel<<<(FEAT * HID / 4 + 255) / 256, 256>>>(
        (const float4*)W1, (__nv_bfloat162*)w1b, FEAT * HID / 4);
    cvt_kernel<<<(HID * HID / 4 + 255) / 256, 256>>>(
        (const float4*)W2, (__nv_bfloat162*)w2b, HID * HID / 4);
    build_wcb_kernel<<<(HID * NOUTP + 255) / 256, 256>>>(Wc, bc, Wb, bb);

    // GEMM1 (split-K=2): Xb [2048,12544] @ W1b -> fp32 partials
    mma_gemm<false, false, false><<<dim3(HID / BN, MROWS / BM, KSPLIT), 256>>>(
        xb, FEAT, w1b, HID, nullptr, part, HID, HID, FEAT / KSPLIT,
        (size_t)MROWS * HID);
    reduce_h1_kernel<<<(MROWS * HID / 4 + 255) / 256, 256>>>(b1);

    // GEMM2: h1b @ W2b + b2 -> relu -> bf16 h2b
    mma_gemm<true, true, true><<<dim3(HID / BN, MROWS / BM, 1), 256>>>(
        h1b, HID, w2b, HID, b2, h2b, HID, HID, HID, 0);

    // Head: h2b @ Wcb + bcb -> fp32 logits+deltas [2048,85]
    mma_gemm<false, true, false><<<dim3(1, MROWS / BM, 1), 256>>>(
        h2b, HID, wcb, NOUTP, bcb, ldp, NOUT, NOUT, HID, 0);

    loss_kernel<<<MROWS, 128>>>(out);
}

// round 9
// speedup vs baseline: 1.1085x; 1.1085x over previous
#include <cuda_runtime.h>
#include <cuda_bf16.h>
#include <math.h>
#include <stdint.h>

// ------------------------ problem constants ------------------------
#define BB_   4
#define NPROP 2000
#define NGT   20
#define FEAT  12544          // 256*7*7
#define HID   1024
#define NCLS  81             // NUM_LABELS + 1
#define NOUT  85             // 81 cls + 4 box
#define NOUTP 128            // padded head width
#define NSAMP 512
#define NPOS  128
#define NNEG  384
#define MROWS (BB_ * NSAMP)  // 2048
#define KSPLIT 2

// ------------------------ device scratch (no allocs allowed) ------------------------
__device__ float          g_part[KSPLIT * MROWS * HID];  // split-K partials
__device__ __nv_bfloat16  g_Xb[MROWS * FEAT];            // gathered + bf16 features
__device__ __nv_bfloat16  g_W1b[FEAT * HID];
__device__ __nv_bfloat16  g_W2b[HID * HID];
__device__ __nv_bfloat16  g_Wcb[HID * NOUTP];
__device__ __nv_bfloat16  g_h1b[MROWS * HID];
__device__ __nv_bfloat16  g_h2b[MROWS * HID];
__device__ float          g_ld[MROWS * NOUT];
__device__ float          g_bcb[NOUTP];
__device__ int            g_sel[MROWS];
__device__ int            g_tgt[MROWS];
__device__ float          g_gtd[MROWS * 4];

// ------------------------ helpers ------------------------
__device__ __forceinline__ unsigned smem_u32(const void* p) {
    return (unsigned)__cvta_generic_to_shared(p);
}
#define CP_ASYNC16(dst_u32, src_ptr) \
    asm volatile("cp.async.cg.shared.global [%0], [%1], 16;" \
                 :: "r"(dst_u32), "l"(src_ptr))
#define CP_COMMIT() asm volatile("cp.async.commit_group;")

__device__ __forceinline__ void ldsm4(unsigned* r, unsigned addr) {
    asm volatile("ldmatrix.sync.aligned.m8n8.x4.shared.b16 {%0,%1,%2,%3}, [%4];"
                 : "=r"(r[0]), "=r"(r[1]), "=r"(r[2]), "=r"(r[3]) : "r"(addr));
}
__device__ __forceinline__ void ldsm4t(unsigned* r, unsigned addr) {
    asm volatile("ldmatrix.sync.aligned.m8n8.x4.trans.shared.b16 {%0,%1,%2,%3}, [%4];"
                 : "=r"(r[0]), "=r"(r[1]), "=r"(r[2]), "=r"(r[3]) : "r"(addr));
}

// ------------------------ small kernels ------------------------

__global__ void zero_out_kernel(float* out) {
    if (threadIdx.x < 2) out[threadIdx.x] = 0.0f;
}

// Per image: IoU matching + threshold labeling + deterministic first-k sampling.
__global__ void select_kernel(const float* __restrict__ proposals,
                              const float* __restrict__ gt_boxes,
                              const int*   __restrict__ gt_labels) {
    int b = blockIdx.x;
    int t = threadIdx.x;  // 256 threads

    __shared__ float gs[NGT][4];
    __shared__ int   glab[NGT];
    __shared__ int   lab[NPROP];
    __shared__ float gtd_sh[NPROP][4];

    if (t < NGT * 4) ((float*)gs)[t] = gt_boxes[b * NGT * 4 + t];
    if (t < NGT)     glab[t] = gt_labels[b * NGT + t];
    for (int i = t; i < NSAMP; i += 256) g_sel[b * NSAMP + i] = -1;
    __syncthreads();

    for (int n = t; n < NPROP; n += 256) {
        const float* p = proposals + (size_t)(b * NPROP + n) * 4;
        float p0 = p[0], p1 = p[1], p2 = p[2], p3 = p[3];
        float ap = (p2 - p0) * (p3 - p1);
        float best = -1.0f; int bi = 0;
        #pragma unroll
        for (int gi = 0; gi < NGT; gi++) {
            float x1 = fmaxf(p0, gs[gi][0]);
            float y1 = fmaxf(p1, gs[gi][1]);
            float x2 = fminf(p2, gs[gi][2]);
            float y2 = fminf(p3, gs[gi][3]);
            float iw = fmaxf(x2 - x1, 0.0f);
            float ih = fmaxf(y2 - y1, 0.0f);
            float inter = iw * ih;
            float ag = (gs[gi][2] - gs[gi][0]) * (gs[gi][3] - gs[gi][1]);
            float iou = inter / (ap + ag - inter);
            if (iou > best) { best = iou; bi = gi; }  // first-max wins
        }
        bool fg = best > 0.5f;
        lab[n] = fg ? glab[bi] : 0;

        float pw = p2 - p0, ph = p3 - p1;
        float pcx = p0 + 0.5f * pw, pcy = p1 + 0.5f * ph;
        float gw = gs[bi][2] - gs[bi][0], gh = gs[bi][3] - gs[bi][1];
        float gcx = 0.5f * (gs[bi][0] + gs[bi][2]);
        float gcy = 0.5f * (gs[bi][1] + gs[bi][3]);
        gtd_sh[n][0] = (gcx - pcx) / pw;
        gtd_sh[n][1] = (gcy - pcy) / ph;
        gtd_sh[n][2] = logf(gw / pw);
        gtd_sh[n][3] = logf(gh / ph);
    }
    __syncthreads();

    if (t == 0) {
        int cpos = 0, cneg = 0;
        for (int n = 0; n < NPROP; n++) {
            int l = lab[n];
            if (l > 0) {
                if (cpos < NPOS) {
                    int s = b * NSAMP + cpos; cpos++;
                    g_sel[s] = b * NPROP + n;
                    g_tgt[s] = l;
                    g_gtd[s * 4 + 0] = gtd_sh[n][0];
                    g_gtd[s * 4 + 1] = gtd_sh[n][1];
                    g_gtd[s * 4 + 2] = gtd_sh[n][2];
                    g_gtd[s * 4 + 3] = gtd_sh[n][3];
                }
            } else {
                if (cneg < NNEG) {
                    int s = b * NSAMP + NPOS + cneg; cneg++;
                    g_sel[s] = b * NPROP + n;
                    g_tgt[s] = 0;
                }
            }
            if (cpos >= NPOS && cneg >= NNEG) break;
        }
    }
}

// Gather selected rows of X and convert fp32 -> bf16 (zero rows for unused slots)
__global__ void cvt_gather_kernel(const float* __restrict__ X) {
    int i = blockIdx.x * 256 + threadIdx.x;        // float4 index
    const int R4 = FEAT / 4;
    if (i >= MROWS * R4) return;
    int r = i / R4, c = i - r * R4;
    int idx = g_sel[r];
    float4 v = make_float4(0.f, 0.f, 0.f, 0.f);
    if (idx >= 0) v = ((const float4*)X)[(size_t)idx * R4 + c];
    __nv_bfloat162* dst = (__nv_bfloat162*)g_Xb;
    dst[2 * i]     = __floats2bfloat162_rn(v.x, v.y);
    dst[2 * i + 1] = __floats2bfloat162_rn(v.z, v.w);
}

// Generic fp32 -> bf16
__global__ void cvt_kernel(const float4* __restrict__ src, __nv_bfloat162* __restrict__ dst, int n4) {
    int i = blockIdx.x * 256 + threadIdx.x;
    if (i < n4) {
        float4 v = src[i];
        dst[2 * i]     = __floats2bfloat162_rn(v.x, v.y);
        dst[2 * i + 1] = __floats2bfloat162_rn(v.z, v.w);
    }
}

// Concatenate [Wc | Wb | 0pad] -> bf16 Wcb[k*128+c], biases fp32
__global__ void build_wcb_kernel(const float* __restrict__ Wc, const float* __restrict__ bc,
                                 const float* __restrict__ Wb, const float* __restrict__ bb) {
    int i = blockIdx.x * 256 + threadIdx.x;
    if (i < HID * NOUTP) {
        int k = i / NOUTP, c = i % NOUTP;
        float v = 0.0f;
        if (c < NCLS)      v = Wc[k * NCLS + c];
        else if (c < NOUT) v = Wb[k * 4 + (c - NCLS)];
        g_Wcb[i] = __float2bfloat16(v);
    }
    if (i < NOUTP) {
        float v = 0.0f;
        if (i < NCLS)      v = bc[i];
        else if (i < NOUT) v = bb[i - NCLS];
        g_bcb[i] = v;
    }
}

// split-K reduce: h1b = bf16(relu(part0 + part1 + bias))
__global__ void reduce_h1_kernel(const float* __restrict__ bias) {
    int i = (blockIdx.x * 256 + threadIdx.x) * 4;
    if (i < MROWS * HID) {
        float4 a = *(const float4*)(g_part + i);
        float4 b = *(const float4*)(g_part + MROWS * HID + i);
        float4 bs = *(const float4*)(bias + (i & (HID - 1)));
        __nv_bfloat162 lo = __floats2bfloat162_rn(fmaxf(a.x + b.x + bs.x, 0.0f),
                                                  fmaxf(a.y + b.y + bs.y, 0.0f));
        __nv_bfloat162 hi = __floats2bfloat162_rn(fmaxf(a.z + b.z + bs.z, 0.0f),
                                                  fmaxf(a.w + b.w + bs.w, 0.0f));
        *(__nv_bfloat162*)(g_h1b + i)     = lo;
        *(__nv_bfloat162*)(g_h1b + i + 2) = hi;
    }
}

// ------------------------ bf16 tensor-core GEMM ------------------------
// Block tile 128x128x32, 256 threads (8 warps, 32x64 warp tiles),
// 4-stage cp.async pipeline, one __syncthreads per K-tile,
// ldmatrix fragment loads, m16n8k16 bf16 MMA.
#define BM 128
#define BN 128
#define BKT 32
#define ASTR 40    // As row stride (bf16)
#define BSTR 136   // Bs row stride (bf16)
#define NSTAGE 4
#define A_STG (BM * ASTR)          // 5120 bf16 per stage
#define B_STG (BKT * BSTR)         // 4352 bf16 per stage
#define SMEM_BYTES ((NSTAGE * (A_STG + B_STG)) * 2)   // 75776

template <bool RELU, bool BIAS, bool OBF16>
__global__ __launch_bounds__(256, 2)
void mma_gemm(const __nv_bfloat16* __restrict__ A, int lda,
              const __nv_bfloat16* __restrict__ B, int ldb,
              const float* __restrict__ bias,
              void* __restrict__ Cv, int ldc, int Nvalid, int Ksub, size_t c_zstride) {
    extern __shared__ __nv_bfloat16 sm[];
    __nv_bfloat16* Asm = sm;                       // [NSTAGE][BM][ASTR]
    __nv_bfloat16* Bsm = sm + NSTAGE * A_STG;      // [NSTAGE][BKT][BSTR]

    const int tid  = threadIdx.x;
    const int lane = tid & 31;
    const int w    = tid >> 5;
    const int wm   = w >> 1;   // 0..3
    const int wn   = w & 1;    // 0..1
    const int bm   = blockIdx.y * BM;
    const int bn   = blockIdx.x * BN;
    const int koff = blockIdx.z * Ksub;

    // A staging: row = tid>>1, 16 bf16 at (tid&1)*16
    const int ar = tid >> 1;
    const int ac = (tid & 1) * 16;
    const __nv_bfloat16* arow = A + (size_t)(bm + ar) * (size_t)lda + koff + ac;

    // B staging: k-row = tid>>3, 16 bf16 at (tid&7)*16
    const int bkr = tid >> 3;
    const int bcc = (tid & 7) * 16;
    const __nv_bfloat16* brow = B + (size_t)(koff + bkr) * (size_t)ldb + bn + bcc;

    float acc[2][8][4];
    #pragma unroll
    for (int i = 0; i < 2; i++)
        #pragma unroll
        for (int j = 0; j < 8; j++)
            #pragma unroll
            for (int q = 0; q < 4; q++) acc[i][j][q] = 0.0f;

    const int T = Ksub / BKT;

    auto stage = [&](int s, int kt) {
        int k0 = kt * BKT;
        __nv_bfloat16* adst = Asm + s * A_STG + ar * ASTR + ac;
        CP_ASYNC16(smem_u32(adst),     arow + k0);
        CP_ASYNC16(smem_u32(adst + 8), arow + k0 + 8);
        const __nv_bfloat16* bs = brow + (size_t)k0 * (size_t)ldb;
        __nv_bfloat16* bdst = Bsm + s * B_STG + bkr * BSTR + bcc;
        CP_ASYNC16(smem_u32(bdst),     bs);
        CP_ASYNC16(smem_u32(bdst + 8), bs + 8);
        CP_COMMIT();
    };

    stage(0, 0);
    stage(1, 1);
    stage(2, 2);

    // ldmatrix lane addressing (verified in R6)
    const int a_r = wm * 32 + (lane & 15);                 // +i*16
    const int a_c = (lane >> 4) * 8;                       // +kk*16
    const int b_r = (lane & 7) + ((lane >> 3) & 1) * 8;    // +kk*16
    const int b_c = wn * 64 + (lane >> 4) * 8;             // +jj*16

    for (int t = 0; t < T; t++) {
        const int rem = T - 1 - t;
        if (rem >= 2)      asm volatile("cp.async.wait_group 2;");
        else if (rem == 1) asm volatile("cp.async.wait_group 1;");
        else               asm volatile("cp.async.wait_group 0;");
        __syncthreads();

        const int s = t & (NSTAGE - 1);
        const __nv_bfloat16* As0 = Asm + s * A_STG;
        const __nv_bfloat16* Bs0 = Bsm + s * B_STG;

        #pragma unroll
        for (int kk = 0; kk < 2; kk++) {
            unsigned a[2][4];
            #pragma unroll
            for (int i = 0; i < 2; i++)
                ldsm4(a[i], smem_u32(As0 + (a_r + i * 16) * ASTR + a_c + kk * 16));

            unsigned b[8][2];
            #pragma unroll
            for (int jj = 0; jj < 4; jj++) {
                unsigned r[4];
                ldsm4t(r, smem_u32(Bs0 + (b_r + kk * 16) * BSTR + b_c + jj * 16));
                b[jj * 2][0] = r[0];     b[jj * 2][1] = r[1];
                b[jj * 2 + 1][0] = r[2]; b[jj * 2 + 1][1] = r[3];
            }

            #pragma unroll
            for (int i = 0; i < 2; i++)
                #pragma unroll
                for (int j = 0; j < 8; j++) {
                    asm volatile(
                        "mma.sync.aligned.m16n8k16.row.col.f32.bf16.bf16.f32 "
                        "{%0,%1,%2,%3}, {%4,%5,%6,%7}, {%8,%9}, {%0,%1,%2,%3};"
                        : "+f"(acc[i][j][0]), "+f"(acc[i][j][1]),
                          "+f"(acc[i][j][2]), "+f"(acc[i][j][3])
                        : "r"(a[i][0]), "r"(a[i][1]), "r"(a[i][2]), "r"(a[i][3]),
                          "r"(b[j][0]), "r"(b[j][1]));
                }
        }

        if (t + 3 < T) stage((t + 3) & (NSTAGE - 1), t + 3);
    }

    if (c_zstride) Cv = (void*)((float*)Cv + (size_t)blockIdx.z * c_zstride);

    // ---- epilogue ----
    const int row0 = bm + wm * 32 + (lane >> 2);
    const int col0 = bn + wn * 64 + (lane & 3) * 2;
    #pragma unroll
    for (int i = 0; i < 2; i++) {
        #pragma unroll
        for (int j = 0; j < 8; j++) {
            int r = row0 + i * 16;
            int c = col0 + j * 8;
            float v0 = acc[i][j][0], v1 = acc[i][j][1];
            float v2 = acc[i][j][2], v3 = acc[i][j][3];
            if (BIAS) {
                float bs0 = __ldg(&bias[c]), bs1 = __ldg(&bias[c + 1]);
                v0 += bs0; v1 += bs1; v2 += bs0; v3 += bs1;
            }
            if (RELU) {
                v0 = fmaxf(v0, 0.f); v1 = fmaxf(v1, 0.f);
                v2 = fmaxf(v2, 0.f); v3 = fmaxf(v3, 0.f);
            }
            if (OBF16) {
                __nv_bfloat16* Cb = (__nv_bfloat16*)Cv;
                *(__nv_bfloat162*)(Cb + (size_t)r * ldc + c)       = __floats2bfloat162_rn(v0, v1);
                *(__nv_bfloat162*)(Cb + (size_t)(r + 8) * ldc + c) = __floats2bfloat162_rn(v2, v3);
            } else if (!BIAS) {
                float* Cf = (float*)Cv;
                *(float2*)(Cf + (size_t)r * ldc + c)       = make_float2(v0, v1);
                *(float2*)(Cf + (size_t)(r + 8) * ldc + c) = make_float2(v2, v3);
            } else {
                float* Cf = (float*)Cv;
                if (c < Nvalid)     Cf[(size_t)r * ldc + c]           = v0;
                if (c + 1 < Nvalid) Cf[(size_t)r * ldc + c + 1]       = v1;
                if (c < Nvalid)     Cf[(size_t)(r + 8) * ldc + c]     = v2;
                if (c + 1 < Nvalid) Cf[(size_t)(r + 8) * ldc + c + 1] = v3;
            }
        }
    }
}

// ------------------------ loss ------------------------
__global__ void loss_kernel(float* __restrict__ out) {
    int r = blockIdx.x;
    if (g_sel[r] < 0) return;
    int t = threadIdx.x;  // 128

    __shared__ float red[128];
    __shared__ float pv[NCLS];

    float l = (t < NCLS) ? g_ld[r * NOUT + t] : -INFINITY;

    red[t] = l; __syncthreads();
    #pragma unroll
    for (int s = 64; s > 0; s >>= 1) {
        if (t < s) red[t] = fmaxf(red[t], red[t + s]);
        __syncthreads();
    }
    float m1 = red[0]; __syncthreads();

    float e = (t < NCLS) ? expf(l - m1) : 0.0f;
    red[t] = e; __syncthreads();
    #pragma unroll
    for (int s = 64; s > 0; s >>= 1) {
        if (t < s) red[t] += red[t + s];
        __syncthreads();
    }
    float S1 = red[0]; __syncthreads();

    float p = e / S1;
    if (t < NCLS) pv[t] = p;

    red[t] = (t < NCLS) ? p : -INFINITY; __syncthreads();
    #pragma unroll
    for (int s = 64; s > 0; s >>= 1) {
        if (t < s) red[t] = fmaxf(red[t], red[t + s]);
        __syncthreads();
    }
    float m2 = red[0]; __syncthreads();

    red[t] = (t < NCLS) ? expf(p - m2) : 0.0f; __syncthreads();
    #pragma unroll
    for (int s = 64; s > 0; s >>= 1) {
        if (t < s) red[t] += red[t + s];
        __syncthreads();
    }
    float S2 = red[0];

    if (t == 0) {
        float lse2 = logf(S2) + m2;
        int tgt = g_tgt[r];
        float nll = -(pv[tgt] - lse2);
        atomicAdd(out, nll * (1.0f / (float)MROWS));
        if (tgt > 0) {
            float s = 0.0f;
            #pragma unroll
            for (int j = 0; j < 4; j++) {
                float d = g_ld[r * NOUT + NCLS + j] - g_gtd[r * 4 + j];
                float ad = fabsf(d);
                s += (ad < 1.0f) ? 0.5f * d * d : ad - 0.5f;
            }
            atomicAdd(out + 1, s * (1.0f / (float)MROWS));
        }
    }
}

// ------------------------ host launcher ------------------------
extern "C" void kernel_launch(void* const* d_in, const int* in_sizes, int n_in,
                              void* d_out, int out_size) {
    const float* X         = (const float*)d_in[0];
    const float* proposals = (const float*)d_in[1];
    const float* gt_boxes  = (const float*)d_in[2];
    const int*   gt_labels = (const int*)  d_in[3];
    const float* W1 = (const float*)d_in[4];
    const float* b1 = (const float*)d_in[5];
    const float* W2 = (const float*)d_in[6];
    const float* b2 = (const float*)d_in[7];
    const float* Wc = (const float*)d_in[8];
    const float* bc = (const float*)d_in[9];
    const float* Wb = (const float*)d_in[10];
    const float* bb = (const float*)d_in[11];
    float* out = (float*)d_out;

    float *part, *ldp, *bcb;
    __nv_bfloat16 *xb, *w1b, *w2b, *wcb, *h1b, *h2b;
    cudaGetSymbolAddress((void**)&part, g_part);
    cudaGetSymbolAddress((void**)&xb,   g_Xb);
    cudaGetSymbolAddress((void**)&w1b,  g_W1b);
    cudaGetSymbolAddress((void**)&w2b,  g_W2b);
    cudaGetSymbolAddress((void**)&wcb,  g_Wcb);
    cudaGetSymbolAddress((void**)&h1b,  g_h1b);
    cudaGetSymbolAddress((void**)&h2b,  g_h2b);
    cudaGetSymbolAddress((void**)&ldp,  g_ld);
    cudaGetSymbolAddress((void**)&bcb,  g_bcb);

    // dynamic smem limit for GEMM instantiations (idempotent, cheap)
    cudaFuncSetAttribute(mma_gemm<false, false, false>,
                         cudaFuncAttributeMaxDynamicSharedMemorySize, SMEM_BYTES);
    cudaFuncSetAttribute(mma_gemm<true, true, true>,
                         cudaFuncAttributeMaxDynamicSharedMemorySize, SMEM_BYTES);
    cudaFuncSetAttribute(mma_gemm<false, true, false>,
                         cudaFuncAttributeMaxDynamicSharedMemorySize, SMEM_BYTES);

    zero_out_kernel<<<1, 32>>>(out);
    select_kernel<<<BB_, 256>>>(proposals, gt_boxes, gt_labels);

    // conversions
    cvt_gather_kernel<<<(MROWS * (FEAT / 4) + 255) / 256, 256>>>(X);
    cvt_kernel<<<(FEAT * HID / 4 + 255) / 256, 256>>>(
        (const float4*)W1, (__nv_bfloat162*)w1b, FEAT * HID / 4);
    cvt_kernel<<<(HID * HID / 4 + 255) / 256, 256>>>(
        (const float4*)W2, (__nv_bfloat162*)w2b, HID * HID / 4);
    build_wcb_kernel<<<(HID * NOUTP + 255) / 256, 256>>>(Wc, bc, Wb, bb);

    // GEMM1 (split-K=2): Xb [2048,12544] @ W1b -> fp32 partials  (grid 8x16x2 = 256)
    mma_gemm<false, false, false><<<dim3(HID / BN, MROWS / BM, KSPLIT), 256, SMEM_BYTES>>>(
        xb, FEAT, w1b, HID, nullptr, part, HID, HID, FEAT / KSPLIT,
        (size_t)MROWS * HID);
    reduce_h1_kernel<<<(MROWS * HID / 4 + 255) / 256, 256>>>(b1);

    // GEMM2: h1b @ W2b + b2 -> relu -> bf16 h2b
    mma_gemm<true, true, true><<<dim3(HID / BN, MROWS / BM, 1), 256, SMEM_BYTES>>>(
        h1b, HID, w2b, HID, b2, h2b, HID, HID, HID, 0);

    // Head: h2b @ Wcb + bcb -> fp32 logits+deltas [2048,85]
    mma_gemm<false, true, false><<<dim3(1, MROWS / BM, 1), 256, SMEM_BYTES>>>(
        h2b, HID, wcb, NOUTP, bcb, ldp, NOUT, NOUT, HID, 0);

    loss_kernel<<<MROWS, 128>>>(out);
}